// round 6
// baseline (speedup 1.0000x reference)
#include <cuda_runtime.h>

// Problem constants (fixed by reference setup)
#define RADIUS2f 100.0f            // (2*RQ)^2
#define PRUNE2f  100.001f          // AABB prune with fp-rounding margin

constexpr int M   = 50000;         // terrain points
constexpr int Q   = 960;           // 4*6*40 query points
constexpr int BP  = 24;            // output elements (B*P)
constexpr int T   = 40;            // trajectory length per (B,P)

constexpr int   GN       = 10;     // grid cells per dim (cell edge == radius)
constexpr float INV_CELL = 0.1f;
constexpr float CELLW    = 10.0f;
constexpr int   NCELL    = GN * GN * GN;   // 1000
constexpr int   CAP      = 128;            // Poisson(50) -> overflow ~1e-19

constexpr int SPLIT = 8;                    // cell-octants per query
constexpr int NWU   = Q * SPLIT;            // 7680 warp work units
constexpr int NT    = 256;                  // threads per block
constexpr int NWPB  = NT / 32;              // 8 warps per block
constexpr int BPSM  = 4;                    // resident blocks per SM (1024 thr/SM)

// Scratch: zero at module load; finalize resets for the next graph replay.
__device__ int      g_cellcnt[NCELL];
__device__ float4   g_cellpts[NCELL * CAP];
__device__ float2   g_part[NWU];            // (cnt, sum) per warp unit
__device__ unsigned g_bar  = 0;
__device__ unsigned g_tick = 0;

__global__ __launch_bounds__(NT, BPSM)
void fused(const float* __restrict__ qg, const float* __restrict__ terr,
           float* __restrict__ out, int nblk) {
    const int tid  = threadIdx.x;
    const int b    = blockIdx.x;
    const int lane = tid & 31;
    const int w    = tid >> 5;

    // ---------------- Phase 1: bin terrain (<=1 point/thread) ----------------
    {
        const int i = b * NT + tid;
        if (i < M) {
            const float x = __ldg(terr + 3 * i + 0);
            const float y = __ldg(terr + 3 * i + 1);
            const float z = __ldg(terr + 3 * i + 2);
            const int cx = min(GN - 1, max(0, (int)(x * INV_CELL)));
            const int cy = min(GN - 1, max(0, (int)(y * INV_CELL)));
            const int cz = min(GN - 1, max(0, (int)(z * INV_CELL)));
            const int c  = (cz * GN + cy) * GN + cx;
            const int slot = atomicAdd(&g_cellcnt[c], 1);
            if (slot < CAP) g_cellpts[c * CAP + slot] = make_float4(x, y, z, 0.f);
        }
    }

    // --------- Grid spin-barrier (all nblk blocks co-resident by design) ---------
    __threadfence();
    __syncthreads();
    if (tid == 0) {
        atomicAdd(&g_bar, 1u);
        while (*(volatile unsigned*)&g_bar < (unsigned)nblk) { }
    }
    __syncthreads();
    __threadfence();   // acquire: bins visible to all readers

    // ------- Phase 2: query, warp per query-octant (block-strided) -------
    for (int gw = b * NWPB + w; gw < NWU; gw += nblk * NWPB) {
        const int qi  = gw >> 3;
        const int oct = gw & 7;

        const float qx = __ldg(qg + 3 * qi + 0);
        const float qy = __ldg(qg + 3 * qi + 1);
        const float qz = __ldg(qg + 3 * qi + 2);
        const int cx = min(GN - 1, max(0, (int)(qx * INV_CELL)));
        const int cy = min(GN - 1, max(0, (int)(qy * INV_CELL)));
        const int cz = min(GN - 1, max(0, (int)(qz * INV_CELL)));

        // Lane-parallel cell setup: lane l < 27 owns neighbor cell l; this
        // warp takes cells where (l & 7) == oct.
        const int dx = lane % 3 - 1;
        const int dy = (lane / 3) % 3 - 1;
        const int dz = lane / 9 - 1;
        const int xx = cx + dx, yy = cy + dy, zz = cz + dz;
        bool valid = (lane < 27) && ((lane & 7) == oct) &&
                     (unsigned)xx < (unsigned)GN && (unsigned)yy < (unsigned)GN &&
                     (unsigned)zz < (unsigned)GN;
        int c = 0, ncell = 0;
        if (valid) {
            // AABB min-distance^2 prune (margin covers fp rounding)
            const float lx = xx * CELLW, ly = yy * CELLW, lz = zz * CELLW;
            const float ex = fmaxf(fmaxf(lx - qx, qx - (lx + CELLW)), 0.f);
            const float ey = fmaxf(fmaxf(ly - qy, qy - (ly + CELLW)), 0.f);
            const float ez = fmaxf(fmaxf(lz - qz, qz - (lz + CELLW)), 0.f);
            if (fmaf(ez, ez, fmaf(ey, ey, ex * ex)) <= PRUNE2f) {
                c = (zz * GN + yy) * GN + xx;
                ncell = min(g_cellcnt[c], CAP);  // surviving counts load in parallel
                valid = (ncell > 0);
            } else valid = false;
        }

        float cnt = 0.f, sum = 0.f;
        unsigned mask = __ballot_sync(0xffffffffu, valid);
        while (mask) {
            const int src = __ffs(mask) - 1;
            mask &= mask - 1;
            const int cc = __shfl_sync(0xffffffffu, c, src);
            const int n  = __shfl_sync(0xffffffffu, ncell, src);
            const float4* __restrict__ pts = g_cellpts + cc * CAP;
            for (int k = lane; k < n; k += 32) {
                const float4 p = __ldg(pts + k);
                const float ddx = qx - p.x, ddy = qy - p.y, ddz = qz - p.z;
                const float d2 = fmaf(ddz, ddz, fmaf(ddy, ddy, ddx * ddx));
                // Exact-d2 classification (validated R1-R5); approx sqrt feeds
                // only the sum (rel err ~1.5e-7 << 1e-3 gate).
                float d;
                asm("sqrt.approx.f32 %0, %1;" : "=f"(d) : "f"(d2));
                if (d2 <= RADIUS2f) { cnt += 1.f; sum += d; }
            }
        }

#pragma unroll
        for (int off = 16; off > 0; off >>= 1) {
            cnt += __shfl_down_sync(0xffffffffu, cnt, off);
            sum += __shfl_down_sync(0xffffffffu, sum, off);
        }
        if (lane == 0) g_part[gw] = make_float2(cnt, sum);
    }

    // ---------- Phase 3: ticket — last block finalizes + resets ----------
    __threadfence();
    __syncthreads();
    __shared__ bool s_last;
    if (tid == 0) s_last = (atomicAdd(&g_tick, 1u) == (unsigned)(nblk - 1));
    __syncthreads();
    if (!s_last) return;
    __threadfence();

    __shared__ float s_pp[Q];
    for (int q2 = tid; q2 < Q; q2 += NT) {
        float cc = 0.f, ss = 0.f;
#pragma unroll
        for (int j = 0; j < SPLIT; j++) {
            const float2 p = g_part[SPLIT * q2 + j];
            cc += p.x; ss += p.y;
        }
        float pp = 0.f;
        if (cc > 0.f) {
            const float dm = ss / cc;
            pp = -(dm * dm) * 0.04f + 4.0f;   // -(dm^2)/RQ^2 + THRESHOLD
        }
        s_pp[q2] = pp;
    }
    __syncthreads();
    if (tid < BP) {
        float acc = 0.f;
#pragma unroll 8
        for (int t = 0; t < T; t++) acc += s_pp[tid * T + t];
        out[tid] = acc;
    }
    // Reset scratch for the next graph replay
    for (int i = tid; i < NCELL; i += NT) g_cellcnt[i] = 0;
    if (tid == 0) { g_bar = 0; g_tick = 0; }
}

extern "C" void kernel_launch(void* const* d_in, const int* in_sizes, int n_in,
                              void* d_out, int out_size) {
    // Inputs per metadata order: [traj (960*3), terrain (50000*3)].
    const float* qptr = (const float*)d_in[0];
    const float* tptr = (const float*)d_in[1];
    if (n_in >= 2 && in_sizes[0] == M * 3 && in_sizes[1] == Q * 3) {
        const float* tmp = qptr; qptr = tptr; tptr = tmp;
    }
    float* out = (float*)d_out;

    int sms = 148;
    cudaDeviceGetAttribute(&sms, cudaDevAttrMultiProcessorCount, 0);
    const int nblk = sms * BPSM;   // all co-resident: 4 blocks/SM x 256 thr, regs<=64

    fused<<<nblk, NT>>>(qptr, tptr, out, nblk);
}

// round 8
// speedup vs baseline: 1.1016x; 1.1016x over previous
#include <cuda_runtime.h>

// Problem constants (fixed by reference setup)
#define RADIUS2f 100.0f            // (2*RQ)^2
#define PRUNE2f  100.001f          // AABB prune with fp-rounding margin

constexpr int M   = 50000;         // terrain points
constexpr int Q   = 960;           // 4*6*40 query points
constexpr int BP  = 24;            // output elements (B*P)
constexpr int T   = 40;            // trajectory length per (B,P)

constexpr int   GN       = 10;     // grid cells per dim (cell edge == radius)
constexpr float INV_CELL = 0.1f;
constexpr float CELLW    = 10.0f;
constexpr int   NCELL    = GN * GN * GN;   // 1000
constexpr int   CAP      = 128;            // Poisson(50) -> overflow ~1e-19

constexpr int SPLIT   = 8;                  // cell-octants per query
constexpr int NWU     = Q * SPLIT;          // 7680 warp work units
constexpr int QNT     = 256;                // query kernel threads/block
constexpr int QNW     = QNT / 32;           // 8 warps/block
constexpr int QBLOCKS = NWU / QNW;          // 960 blocks
constexpr int NSLOT   = 4;                  // max cells per warp (27/8 rounded up)

// Scratch: zero at module load; finalize resets for the next graph replay.
__device__ int      g_cellcnt[NCELL];
__device__ float4   g_cellpts[NCELL * CAP];
__device__ float2   g_part[NWU];            // (cnt, sum) per warp unit
__device__ unsigned g_tick = 0;

// ---------------- Kernel A: bin terrain into the 10^3 grid ----------------
__global__ __launch_bounds__(256)
void bin_kernel(const float* __restrict__ terr) {
    const int i = blockIdx.x * 256 + threadIdx.x;
    if (i >= M) return;
    const float x = __ldg(terr + 3 * i + 0);
    const float y = __ldg(terr + 3 * i + 1);
    const float z = __ldg(terr + 3 * i + 2);
    const int cx = min(GN - 1, max(0, (int)(x * INV_CELL)));
    const int cy = min(GN - 1, max(0, (int)(y * INV_CELL)));
    const int cz = min(GN - 1, max(0, (int)(z * INV_CELL)));
    const int c  = (cz * GN + cy) * GN + cx;
    const int slot = atomicAdd(&g_cellcnt[c], 1);
    if (slot < CAP) g_cellpts[c * CAP + slot] = make_float4(x, y, z, 0.f);
}

__device__ __forceinline__ void accum_pt(const float4 p, float qx, float qy, float qz,
                                         float& cnt, float& sum) {
    const float ddx = qx - p.x, ddy = qy - p.y, ddz = qz - p.z;
    const float d2 = fmaf(ddz, ddz, fmaf(ddy, ddy, ddx * ddx));
    // Exact-d2 classification (validated R1-R6); approx sqrt feeds only the
    // sum (rel err ~1.5e-7 << 1e-3 gate). Sentinel points (1e9) self-exclude.
    float d;
    asm("sqrt.approx.f32 %0, %1;" : "=f"(d) : "f"(d2));
    if (d2 <= RADIUS2f) { cnt += 1.f; sum += d; }
}

// ------- Kernel B: query (warp per query-octant, batched loads) + finalize -------
__global__ __launch_bounds__(QNT)
void query_kernel(const float* __restrict__ qg, float* __restrict__ out) {
    const int tid  = threadIdx.x;
    const int lane = tid & 31;
    const int gw   = blockIdx.x * QNW + (tid >> 5);   // 0..NWU-1
    const int qi   = gw >> 3;
    const int oct  = gw & 7;

    const float qx = __ldg(qg + 3 * qi + 0);
    const float qy = __ldg(qg + 3 * qi + 1);
    const float qz = __ldg(qg + 3 * qi + 2);
    const int cx = min(GN - 1, max(0, (int)(qx * INV_CELL)));
    const int cy = min(GN - 1, max(0, (int)(qy * INV_CELL)));
    const int cz = min(GN - 1, max(0, (int)(qz * INV_CELL)));

    // Lane-parallel cell setup: lane l < 27 owns neighbor cell l.
    const int dx = lane % 3 - 1;
    const int dy = (lane / 3) % 3 - 1;
    const int dz = lane / 9 - 1;
    const int xx = cx + dx, yy = cy + dy, zz = cz + dz;
    bool valid = (lane < 27) &&
                 (unsigned)xx < (unsigned)GN && (unsigned)yy < (unsigned)GN &&
                 (unsigned)zz < (unsigned)GN;
    int c = 0, myn = 0;   // lanes >=27 and pruned lanes keep myn=0
    if (valid) {
        // AABB min-distance^2 prune (margin covers fp rounding)
        const float lx = xx * CELLW, ly = yy * CELLW, lz = zz * CELLW;
        const float ex = fmaxf(fmaxf(lx - qx, qx - (lx + CELLW)), 0.f);
        const float ey = fmaxf(fmaxf(ly - qy, qy - (ly + CELLW)), 0.f);
        const float ez = fmaxf(fmaxf(lz - qz, qz - (lz + CELLW)), 0.f);
        if (fmaf(ez, ez, fmaf(ey, ey, ex * ex)) <= PRUNE2f) {
            c = (zz * GN + yy) * GN + xx;
            myn = min(g_cellcnt[c], CAP);   // counts for all 27 cells load in parallel
        }
    }

    // Broadcast this warp's (<=4) cells: lanes {oct, oct+8, oct+16, oct+24}.
    const float4* __restrict__ base[NSLOT];
    int ns[NSLOT];
#pragma unroll
    for (int s = 0; s < NSLOT; s++) {
        const int src = oct + 8 * s;            // < 32; lanes >=27 carry myn=0
        const int cc  = __shfl_sync(0xffffffffu, c,   src);
        ns[s]         = __shfl_sync(0xffffffffu, myn, src);
        base[s]       = g_cellpts + cc * CAP;   // hoisted address math
    }
    const int nmax = max(max(ns[0], ns[1]), max(ns[2], ns[3]));

    float cnt = 0.f, sum = 0.f;
    for (int k0 = 0; k0 < nmax; k0 += 64) {
        // Issue all 8 (4 cells x 2 strides) predicated loads before accumulating.
        float4 P[NSLOT][2];
#pragma unroll
        for (int s = 0; s < NSLOT; s++) {
#pragma unroll
            for (int j = 0; j < 2; j++) {
                const int k = k0 + lane + 32 * j;
                P[s][j] = (k < ns[s]) ? __ldg(base[s] + k)
                                      : make_float4(1e9f, 1e9f, 1e9f, 0.f);
            }
        }
#pragma unroll
        for (int s = 0; s < NSLOT; s++) {
#pragma unroll
            for (int j = 0; j < 2; j++)
                accum_pt(P[s][j], qx, qy, qz, cnt, sum);
        }
    }

#pragma unroll
    for (int off = 16; off > 0; off >>= 1) {
        cnt += __shfl_down_sync(0xffffffffu, cnt, off);
        sum += __shfl_down_sync(0xffffffffu, sum, off);
    }
    if (lane == 0) g_part[gw] = make_float2(cnt, sum);

    // ---------- Ticket: last block finalizes + resets ----------
    __threadfence();
    __syncthreads();
    __shared__ bool s_last;
    if (tid == 0) s_last = (atomicAdd(&g_tick, 1u) == (unsigned)(QBLOCKS - 1));
    __syncthreads();
    if (!s_last) return;
    __threadfence();

    __shared__ float s_pp[Q];
    for (int q2 = tid; q2 < Q; q2 += QNT) {
        float cc = 0.f, ss = 0.f;
#pragma unroll
        for (int j = 0; j < SPLIT; j++) {
            const float2 p = g_part[SPLIT * q2 + j];
            cc += p.x; ss += p.y;
        }
        float pp = 0.f;
        if (cc > 0.f) {
            const float dm = ss / cc;
            pp = -(dm * dm) * 0.04f + 4.0f;   // -(dm^2)/RQ^2 + THRESHOLD
        }
        s_pp[q2] = pp;
    }
    __syncthreads();
    if (tid < BP) {
        float acc = 0.f;
#pragma unroll 8
        for (int t = 0; t < T; t++) acc += s_pp[tid * T + t];
        out[tid] = acc;
    }
    // Reset scratch for the next graph replay
    for (int i = tid; i < NCELL; i += QNT) g_cellcnt[i] = 0;
    if (tid == 0) g_tick = 0;
}

extern "C" void kernel_launch(void* const* d_in, const int* in_sizes, int n_in,
                              void* d_out, int out_size) {
    // Inputs per metadata order: [traj (960*3), terrain (50000*3)].
    const float* qptr = (const float*)d_in[0];
    const float* tptr = (const float*)d_in[1];
    if (n_in >= 2 && in_sizes[0] == M * 3 && in_sizes[1] == Q * 3) {
        const float* tmp = qptr; qptr = tptr; tptr = tmp;
    }
    float* out = (float*)d_out;

    bin_kernel<<<(M + 255) / 256, 256>>>(tptr);
    query_kernel<<<QBLOCKS, QNT>>>(qptr, out);
}